// round 8
// baseline (speedup 1.0000x reference)
#include <cuda_runtime.h>
#include <cuda_bf16.h>
#include <cstdint>

// ---------------- problem constants ----------------
#define BATCH 512
#define NEQv  4096
#define XDIMv 6144
#define H1v   2048
#define H2v   2048
#define YDIMv 4096
#define NEDGE 32768

// ---------------- scratch (device globals; no runtime alloc) ----------------
__device__ __align__(256) __nv_bfloat16 g_z0h[BATCH * XDIMv];
__device__ __align__(256) __nv_bfloat16 g_z0l[BATCH * XDIMv];
__device__ __align__(256) __nv_bfloat16 g_z1h[BATCH * H1v];
__device__ __align__(256) __nv_bfloat16 g_z1l[BATCH * H1v];
__device__ __align__(256) __nv_bfloat16 g_z2h[BATCH * H2v];
__device__ __align__(256) __nv_bfloat16 g_z2l[BATCH * H2v];
__device__ __align__(256) __nv_bfloat16 g_w1h[XDIMv * H1v];
__device__ __align__(256) __nv_bfloat16 g_w1l[XDIMv * H1v];
__device__ __align__(256) __nv_bfloat16 g_w2h[H1v * H2v];
__device__ __align__(256) __nv_bfloat16 g_w2l[H1v * H2v];
__device__ __align__(256) __nv_bfloat16 g_w3h[H2v * YDIMv];
__device__ __align__(256) __nv_bfloat16 g_w3l[H2v * YDIMv];
__device__ int   g_cnt[NEQv];
__device__ float g_acc[NEQv];

// ============================================================
// helpers
// ============================================================
__device__ __forceinline__ unsigned smem_u32(const void* p) {
    return (unsigned)__cvta_generic_to_shared(p);
}
__device__ __forceinline__ void cp16(void* dst, const void* src) {
    asm volatile("cp.async.ca.shared.global [%0], [%1], 16;\n"
                 :: "r"(smem_u32(dst)), "l"(src));
}
#define CP_COMMIT() asm volatile("cp.async.commit_group;\n")
#define CP_WAIT1()  asm volatile("cp.async.wait_group 1;\n")

#define MMA_BF16(C, A, B)                                                        \
    asm volatile("mma.sync.aligned.m16n8k16.row.col.f32.bf16.bf16.f32 "          \
                 "{%0,%1,%2,%3},{%4,%5,%6,%7},{%8,%9},{%0,%1,%2,%3};\n"          \
                 : "+f"((C)[0]), "+f"((C)[1]), "+f"((C)[2]), "+f"((C)[3])         \
                 : "r"((A)[0]), "r"((A)[1]), "r"((A)[2]), "r"((A)[3]),            \
                   "r"((B)[0]), "r"((B)[1]))

// split f0,f1 -> packed bf16x2 hi (trunc) + bf16x2 lo (rn residual). R6/R7-proven.
__device__ __forceinline__ void packsplit(float f0, float f1, uint32_t& hi, uint32_t& lo) {
    uint32_t u0 = __float_as_uint(f0), u1 = __float_as_uint(f1);
    hi = __byte_perm(u0, u1, 0x7632);
    float l0 = f0 - __uint_as_float(u0 & 0xFFFF0000u);
    float l1 = f1 - __uint_as_float(u1 & 0xFFFF0000u);
    __nv_bfloat162 p = __floats2bfloat162_rn(l0, l1);
    lo = *(uint32_t*)&p;
}
__device__ __forceinline__ uint32_t merge16(uint32_t lo16, uint32_t hi16) {
    return lo16 | (hi16 << 16);
}

// ============================================================
// GCN kernels
// ============================================================
__global__ void k_init() {
    int i = blockIdx.x * blockDim.x + threadIdx.x;
    if (i < NEQv) { g_cnt[i] = 0; g_acc[i] = 0.f; }
}
__global__ void k_count(const int* __restrict__ ei) {
    int e = blockIdx.x * blockDim.x + threadIdx.x;
    if (e < NEDGE) atomicAdd(&g_cnt[ei[NEDGE + e]], 1);
}
__global__ void k_scatter(const int* __restrict__ ei, const float* __restrict__ x,
                          const float* __restrict__ gw) {
    int e = blockIdx.x * blockDim.x + threadIdx.x;
    if (e >= NEDGE) return;
    int s = ei[e];
    int d = ei[NEDGE + e];
    float deg_s = 1.f + 512.f * (float)g_cnt[s];
    float xw = gw[0] * x[(size_t)(s & 511) * XDIMv + (s >> 9)];
    atomicAdd(&g_acc[d], rsqrtf(deg_s) * xw);
}
// writes split activations directly (two consecutive columns per thread)
__global__ void k_build_z(const float* __restrict__ x, const float* __restrict__ gw,
                          const float* __restrict__ gb) {
    int idx2 = blockIdx.x * blockDim.x + threadIdx.x;   // pair index
    if (idx2 >= BATCH * XDIMv / 2) return;
    int idx = idx2 * 2;
    int b = idx / XDIMv;
    int j = idx - b * XDIMv;
    float2 v = *(const float2*)&x[idx];
    float z0, z1;
    if (j >= NEQv) {
        z0 = v.x; z1 = v.y;
    } else {
        float w = gw[0], bb = gb[0];
        float xw0 = w * v.x, xw1 = w * v.y;
        float o0, o1;
        if (j < 8) {   // j, j+1 both < 8 only if j<8 (j even); handle each
            int i0 = (j << 9) + b;
            float deg0 = 1.f + 512.f * (float)g_cnt[i0];
            o0 = xw0 / deg0 + 512.f * rsqrtf(deg0) * g_acc[i0] + bb;
            if (j + 1 < 8) {
                int i1 = ((j + 1) << 9) + b;
                float deg1 = 1.f + 512.f * (float)g_cnt[i1];
                o1 = xw1 / deg1 + 512.f * rsqrtf(deg1) * g_acc[i1] + bb;
            } else {
                o1 = xw1 + bb;
            }
        } else {
            o0 = xw0 + bb;
            o1 = xw1 + bb;
        }
        z0 = fmaxf(o0, 0.f);
        z1 = fmaxf(o1, 0.f);
    }
    uint32_t h, l;
    packsplit(z0, z1, h, l);
    *(uint32_t*)&g_z0h[idx] = h;
    *(uint32_t*)&g_z0l[idx] = l;
}

// ============================================================
// weight split (elementwise, natural [K,N] layout) — R7-proven
// ============================================================
__global__ void k_wsplit(const float* __restrict__ W, __nv_bfloat16* __restrict__ Wh,
                         __nv_bfloat16* __restrict__ Wl, int n4) {
    int i = blockIdx.x * blockDim.x + threadIdx.x;
    if (i >= n4) return;
    float4 v = ((const float4*)W)[i];
    uint2 h, l;
    packsplit(v.x, v.y, h.x, l.x);
    packsplit(v.z, v.w, h.y, l.y);
    ((uint2*)Wh)[i] = h;
    ((uint2*)Wl)[i] = l;
}

// ============================================================
// GEMM: C[M,N] = act(A[M,K] @ W[K,N] + bias)
// A: pre-split bf16 Ah/Al [M,K] -> bf16 smem -> LDS.32 fragments
// B: pre-split bf16 Wh/Wl [K,N] -> bf16 smem -> LDS.16 + merge (R7-proven)
// mma.m16n8k16.bf16, 3-term split accumulate.
// ============================================================
#define BM 128
#define BN 64
#define BK 32
#define APITCH 40                      // bf16 per A smem row (80 B)
#define BPITCH 72                      // bf16 per B smem row (144 B)
#define A_BYTES (BM * APITCH * 2)      // 10240 per half
#define B_BYTES (BK * BPITCH * 2)      //  4608 per half
#define STAGE_BYTES (2 * A_BYTES + 2 * B_BYTES)   // 29696
#define STAGES 3
#define GEMM_SMEM_BYTES (STAGES * STAGE_BYTES)    // 89088

template<int RELU>   // RELU=1: split bf16 outputs (next layer); 0: float out
__global__ void __launch_bounds__(256, 2) k_gemm(
    const __nv_bfloat16* __restrict__ Ah, const __nv_bfloat16* __restrict__ Al,
    const __nv_bfloat16* __restrict__ Wh, const __nv_bfloat16* __restrict__ Wl,
    const float* __restrict__ bias,
    void* __restrict__ out1, void* __restrict__ out2,
    int M, int N, int K)
{
    extern __shared__ char smem[];
    const int tid  = threadIdx.x;
    const int lane = tid & 31;
    const int wid  = tid >> 5;
    const int wm   = wid & 3;        // 4 warps in M -> 32 rows each
    const int wn   = wid >> 2;       // 2 warps in N -> 32 cols each
    const int m0   = blockIdx.y * BM;
    const int n0   = blockIdx.x * BN;
    const int r    = lane >> 2;      // 0..7
    const int q    = lane & 3;       // 0..3

    float c[2][4][4];
#pragma unroll
    for (int i = 0; i < 2; i++)
#pragma unroll
        for (int j = 0; j < 4; j++)
#pragma unroll
            for (int k = 0; k < 4; k++) c[i][j][k] = 0.f;

    const int kIters = K / BK;

    auto loadStage = [&](int it, int stg) {
        const int k0 = it * BK;
        char* st = smem + stg * STAGE_BYTES;
        // A: 2 halves x 128 rows x 4 chunks of 16B (bf16, 32 bf16/row data)
#pragma unroll
        for (int t = 0; t < 4; t++) {
            int id = tid + t * 256;          // 0..1023
            int a  = id >> 9;                // 0=h, 1=l
            int rb = id & 511;
            int rr = rb >> 2, ch = rb & 3;
            const __nv_bfloat16* src = (a ? Al : Ah) + (size_t)(m0 + rr) * K + k0 + ch * 8;
            cp16(st + a * A_BYTES + rr * (APITCH * 2) + ch * 16, src);
        }
        // B: 2 halves x 32 rows x 8 chunks of 16B
#pragma unroll
        for (int t = 0; t < 2; t++) {
            int id = tid + t * 256;          // 0..511
            int a  = id >> 8;
            int rb = id & 255;
            int rr = rb >> 3, ch = rb & 7;
            const __nv_bfloat16* src = (a ? Wl : Wh) + (size_t)(k0 + rr) * N + n0 + ch * 8;
            cp16(st + 2 * A_BYTES + a * B_BYTES + rr * (BPITCH * 2) + ch * 16, src);
        }
    };

    loadStage(0, 0); CP_COMMIT();
    loadStage(1, 1); CP_COMMIT();

    for (int it = 0; it < kIters; ++it) {
        CP_WAIT1();
        __syncthreads();
        if (it + 2 < kIters) loadStage(it + 2, (it + 2) % STAGES);
        CP_COMMIT();

        const char* st  = smem + (it % STAGES) * STAGE_BYTES;
        const char* sAh = st;
        const char* sAl = st + A_BYTES;
        const char* sBh = st + 2 * A_BYTES;
        const char* sBl = st + 2 * A_BYTES + B_BYTES;

#pragma unroll
        for (int kk = 0; kk < BK; kk += 16) {
            uint32_t ah[2][4], al[2][4], bh[4][2], bl[4][2];
#pragma unroll
            for (int mt = 0; mt < 2; mt++) {
                const int ab = (wm * 32 + mt * 16 + r) * (APITCH * 2) + (kk + 2 * q) * 2;
                ah[mt][0] = *(const uint32_t*)(sAh + ab);
                ah[mt][1] = *(const uint32_t*)(sAh + ab + 8 * APITCH * 2);
                ah[mt][2] = *(const uint32_t*)(sAh + ab + 16);
                ah[mt][3] = *(const uint32_t*)(sAh + ab + 8 * APITCH * 2 + 16);
                al[mt][0] = *(const uint32_t*)(sAl + ab);
                al[mt][1] = *(const uint32_t*)(sAl + ab + 8 * APITCH * 2);
                al[mt][2] = *(const uint32_t*)(sAl + ab + 16);
                al[mt][3] = *(const uint32_t*)(sAl + ab + 8 * APITCH * 2 + 16);
            }
#pragma unroll
            for (int nt = 0; nt < 4; nt++) {
                const int n  = wn * 32 + nt * 8 + r;
                const int kb = (kk + 2 * q) * (BPITCH * 2) + n * 2;
                uint32_t h00 = *(const uint16_t*)(sBh + kb);
                uint32_t h01 = *(const uint16_t*)(sBh + kb + BPITCH * 2);
                uint32_t h10 = *(const uint16_t*)(sBh + kb + 8 * BPITCH * 2);
                uint32_t h11 = *(const uint16_t*)(sBh + kb + 9 * BPITCH * 2);
                bh[nt][0] = merge16(h00, h01);
                bh[nt][1] = merge16(h10, h11);
                uint32_t l00 = *(const uint16_t*)(sBl + kb);
                uint32_t l01 = *(const uint16_t*)(sBl + kb + BPITCH * 2);
                uint32_t l10 = *(const uint16_t*)(sBl + kb + 8 * BPITCH * 2);
                uint32_t l11 = *(const uint16_t*)(sBl + kb + 9 * BPITCH * 2);
                bl[nt][0] = merge16(l00, l01);
                bl[nt][1] = merge16(l10, l11);
            }
            // 3 split terms; each sweep = 8 independent accumulators (ILP)
#pragma unroll
            for (int mt = 0; mt < 2; mt++)
#pragma unroll
                for (int nt = 0; nt < 4; nt++)
                    MMA_BF16(c[mt][nt], ah[mt], bh[nt]);
#pragma unroll
            for (int mt = 0; mt < 2; mt++)
#pragma unroll
                for (int nt = 0; nt < 4; nt++)
                    MMA_BF16(c[mt][nt], ah[mt], bl[nt]);
#pragma unroll
            for (int mt = 0; mt < 2; mt++)
#pragma unroll
                for (int nt = 0; nt < 4; nt++)
                    MMA_BF16(c[mt][nt], al[mt], bh[nt]);
        }
    }

    // ---------------- epilogue ----------------
#pragma unroll
    for (int mt = 0; mt < 2; mt++) {
#pragma unroll
        for (int nt = 0; nt < 4; nt++) {
            int row0 = m0 + wm * 32 + mt * 16 + r;
            int col0 = n0 + wn * 32 + nt * 8 + 2 * q;
            float bb0 = bias[col0], bb1 = bias[col0 + 1];
            float v00 = c[mt][nt][0] + bb0, v01 = c[mt][nt][1] + bb1;
            float v10 = c[mt][nt][2] + bb0, v11 = c[mt][nt][3] + bb1;
            if (RELU) {
                v00 = fmaxf(v00, 0.f); v01 = fmaxf(v01, 0.f);
                v10 = fmaxf(v10, 0.f); v11 = fmaxf(v11, 0.f);
                __nv_bfloat16* zh = (__nv_bfloat16*)out1;
                __nv_bfloat16* zl = (__nv_bfloat16*)out2;
                uint32_t h0, l0, h1, l1;
                packsplit(v00, v01, h0, l0);
                packsplit(v10, v11, h1, l1);
                size_t i0 = (size_t)row0 * N + col0;
                size_t i1 = (size_t)(row0 + 8) * N + col0;
                *(uint32_t*)&zh[i0] = h0;  *(uint32_t*)&zl[i0] = l0;
                *(uint32_t*)&zh[i1] = h1;  *(uint32_t*)&zl[i1] = l1;
            } else {
                float* o = (float*)out1;
                *(float2*)&o[(size_t)row0 * N + col0]       = make_float2(v00, v01);
                *(float2*)&o[(size_t)(row0 + 8) * N + col0] = make_float2(v10, v11);
            }
        }
    }
}

// ============================================================
// launch
// ============================================================
extern "C" void kernel_launch(void* const* d_in, const int* in_sizes, int n_in,
                              void* d_out, int out_size) {
    const float* x  = (const float*)d_in[0];
    const int*   ei = (const int*)  d_in[1];
    const float* gw = (const float*)d_in[2];
    const float* gb = (const float*)d_in[3];
    const float* W1 = (const float*)d_in[4];
    const float* b1 = (const float*)d_in[5];
    const float* W2 = (const float*)d_in[6];
    const float* b2 = (const float*)d_in[7];
    const float* W3 = (const float*)d_in[8];
    const float* b3 = (const float*)d_in[9];
    float* out = (float*)d_out;

    cudaFuncSetAttribute(k_gemm<1>, cudaFuncAttributeMaxDynamicSharedMemorySize, GEMM_SMEM_BYTES);
    cudaFuncSetAttribute(k_gemm<0>, cudaFuncAttributeMaxDynamicSharedMemorySize, GEMM_SMEM_BYTES);

    void *z0hp, *z0lp, *z1hp, *z1lp, *z2hp, *z2lp;
    void *w1hp, *w1lp, *w2hp, *w2lp, *w3hp, *w3lp;
    cudaGetSymbolAddress(&z0hp, g_z0h); cudaGetSymbolAddress(&z0lp, g_z0l);
    cudaGetSymbolAddress(&z1hp, g_z1h); cudaGetSymbolAddress(&z1lp, g_z1l);
    cudaGetSymbolAddress(&z2hp, g_z2h); cudaGetSymbolAddress(&z2lp, g_z2l);
    cudaGetSymbolAddress(&w1hp, g_w1h); cudaGetSymbolAddress(&w1lp, g_w1l);
    cudaGetSymbolAddress(&w2hp, g_w2h); cudaGetSymbolAddress(&w2lp, g_w2l);
    cudaGetSymbolAddress(&w3hp, g_w3h); cudaGetSymbolAddress(&w3lp, g_w3l);

    // weight splits
    k_wsplit<<<(XDIMv * H1v / 4 + 255) / 256, 256>>>(W1, (__nv_bfloat16*)w1hp, (__nv_bfloat16*)w1lp, XDIMv * H1v / 4);
    k_wsplit<<<(H1v * H2v / 4 + 255) / 256, 256>>>(W2, (__nv_bfloat16*)w2hp, (__nv_bfloat16*)w2lp, H1v * H2v / 4);
    k_wsplit<<<(H2v * YDIMv / 4 + 255) / 256, 256>>>(W3, (__nv_bfloat16*)w3hp, (__nv_bfloat16*)w3lp, H2v * YDIMv / 4);

    // GCN
    k_init<<<NEQv / 256, 256>>>();
    k_count<<<NEDGE / 256, 256>>>(ei);
    k_scatter<<<NEDGE / 256, 256>>>(ei, x, gw);
    k_build_z<<<(BATCH * XDIMv / 2) / 256, 256>>>(x, gw, gb);

    // MLP
    dim3 g1(H1v / BN,   BATCH / BM);
    dim3 g2(H2v / BN,   BATCH / BM);
    dim3 g3(YDIMv / BN, BATCH / BM);
    k_gemm<1><<<g1, 256, GEMM_SMEM_BYTES>>>(
        (const __nv_bfloat16*)z0hp, (const __nv_bfloat16*)z0lp,
        (const __nv_bfloat16*)w1hp, (const __nv_bfloat16*)w1lp,
        b1, z1hp, z1lp, BATCH, H1v, XDIMv);
    k_gemm<1><<<g2, 256, GEMM_SMEM_BYTES>>>(
        (const __nv_bfloat16*)z1hp, (const __nv_bfloat16*)z1lp,
        (const __nv_bfloat16*)w2hp, (const __nv_bfloat16*)w2lp,
        b2, z2hp, z2lp, BATCH, H2v, H1v);
    k_gemm<0><<<g3, 256, GEMM_SMEM_BYTES>>>(
        (const __nv_bfloat16*)z2hp, (const __nv_bfloat16*)z2lp,
        (const __nv_bfloat16*)w3hp, (const __nv_bfloat16*)w3lp,
        b3, out, nullptr, BATCH, YDIMv, H2v);
}

// round 9
// speedup vs baseline: 1.3851x; 1.3851x over previous
#include <cuda_runtime.h>
#include <cuda_fp16.h>
#include <cstdint>

// ---------------- problem constants ----------------
#define BATCH 512
#define NEQv  4096
#define XDIMv 6144
#define H1v   2048
#define H2v   2048
#define YDIMv 4096
#define NEDGE 32768

// ---------------- scratch (device globals; no runtime alloc) ----------------
__device__ __align__(256) __half g_z0[BATCH * XDIMv];   // fp16 activations
__device__ __align__(256) __half g_z1[BATCH * H1v];
__device__ __align__(256) __half g_z2[BATCH * H2v];
__device__ __align__(256) __half g_w1h[XDIMv * H1v];    // fp16 weight pairs
__device__ __align__(256) __half g_w1l[XDIMv * H1v];
__device__ __align__(256) __half g_w2h[H1v * H2v];
__device__ __align__(256) __half g_w2l[H1v * H2v];
__device__ __align__(256) __half g_w3h[H2v * YDIMv];
__device__ __align__(256) __half g_w3l[H2v * YDIMv];
__device__ int   g_cnt[NEQv];
__device__ float g_acc[NEQv];

// ============================================================
// helpers
// ============================================================
__device__ __forceinline__ unsigned smem_u32(const void* p) {
    return (unsigned)__cvta_generic_to_shared(p);
}
__device__ __forceinline__ void cp16(void* dst, const void* src) {
    asm volatile("cp.async.ca.shared.global [%0], [%1], 16;\n"
                 :: "r"(smem_u32(dst)), "l"(src));
}
#define CP_COMMIT() asm volatile("cp.async.commit_group;\n")
#define CP_WAIT1()  asm volatile("cp.async.wait_group 1;\n")

#define MMA_F16(C, A, B)                                                         \
    asm volatile("mma.sync.aligned.m16n8k16.row.col.f32.f16.f16.f32 "            \
                 "{%0,%1,%2,%3},{%4,%5,%6,%7},{%8,%9},{%0,%1,%2,%3};\n"          \
                 : "+f"((C)[0]), "+f"((C)[1]), "+f"((C)[2]), "+f"((C)[3])         \
                 : "r"((A)[0]), "r"((A)[1]), "r"((A)[2]), "r"((A)[3]),            \
                   "r"((B)[0]), "r"((B)[1]))

__device__ __forceinline__ uint32_t merge16(uint32_t lo16, uint32_t hi16) {
    return lo16 | (hi16 << 16);
}
// fp16 pair split: h = rn(f), l = rn(f - float(h));  (f - float(h)) exact (Sterbenz)
__device__ __forceinline__ void hsplit2(float f0, float f1, uint32_t& h, uint32_t& l) {
    __half2 hh = __floats2half2_rn(f0, f1);
    float2 hf = __half22float2(hh);
    __half2 ll = __floats2half2_rn(f0 - hf.x, f1 - hf.y);
    h = *(uint32_t*)&hh;
    l = *(uint32_t*)&ll;
}

// ============================================================
// fused init + weight split (all 3 weight matrices, fp16 pairs)
// ============================================================
#define N1_4 (XDIMv * H1v / 4)
#define N2_4 (H1v * H2v / 4)
#define N3_4 (H2v * YDIMv / 4)
__global__ void k_wsplit_all(const float* __restrict__ W1, const float* __restrict__ W2,
                             const float* __restrict__ W3) {
    int i = blockIdx.x * blockDim.x + threadIdx.x;
    if (i < NEQv) { g_cnt[i] = 0; g_acc[i] = 0.f; }
    const float* W; __half* H; __half* L; int j;
    if (i < N1_4) {
        W = W1; H = g_w1h; L = g_w1l; j = i;
    } else if (i < N1_4 + N2_4) {
        W = W2; H = g_w2h; L = g_w2l; j = i - N1_4;
    } else {
        W = W3; H = g_w3h; L = g_w3l; j = i - (N1_4 + N2_4);
    }
    float4 v = ((const float4*)W)[j];
    uint2 h, l;
    hsplit2(v.x, v.y, h.x, l.x);
    hsplit2(v.z, v.w, h.y, l.y);
    ((uint2*)H)[j] = h;
    ((uint2*)L)[j] = l;
}

// ============================================================
// GCN kernels
// ============================================================
__global__ void k_count(const int* __restrict__ ei) {
    int e = blockIdx.x * blockDim.x + threadIdx.x;
    if (e < NEDGE) atomicAdd(&g_cnt[ei[NEDGE + e]], 1);
}
__global__ void k_scatter(const int* __restrict__ ei, const float* __restrict__ x,
                          const float* __restrict__ gw) {
    int e = blockIdx.x * blockDim.x + threadIdx.x;
    if (e >= NEDGE) return;
    int s = ei[e];
    int d = ei[NEDGE + e];
    float deg_s = 1.f + 512.f * (float)g_cnt[s];
    float xw = gw[0] * x[(size_t)(s & 511) * XDIMv + (s >> 9)];
    atomicAdd(&g_acc[d], rsqrtf(deg_s) * xw);
}
// 2D grid: y = batch row, x covers column pairs (no integer division)
__global__ void k_build_z(const float* __restrict__ x, const float* __restrict__ gw,
                          const float* __restrict__ gb) {
    int j = (blockIdx.x * blockDim.x + threadIdx.x) * 2;
    int b = blockIdx.y;
    float2 v = *(const float2*)&x[(size_t)b * XDIMv + j];
    float z0, z1;
    if (j >= NEQv) {
        z0 = v.x; z1 = v.y;
    } else {
        float w = gw[0], bb = gb[0];
        float xw0 = w * v.x, xw1 = w * v.y;
        float o0, o1;
        if (j < 8) {
            int i0 = (j << 9) + b;
            float deg0 = 1.f + 512.f * (float)g_cnt[i0];
            o0 = xw0 / deg0 + 512.f * rsqrtf(deg0) * g_acc[i0] + bb;
            if (j + 1 < 8) {
                int i1 = ((j + 1) << 9) + b;
                float deg1 = 1.f + 512.f * (float)g_cnt[i1];
                o1 = xw1 / deg1 + 512.f * rsqrtf(deg1) * g_acc[i1] + bb;
            } else {
                o1 = xw1 + bb;
            }
        } else {
            o0 = xw0 + bb;
            o1 = xw1 + bb;
        }
        z0 = fmaxf(o0, 0.f);
        z1 = fmaxf(o1, 0.f);
    }
    __half2 p = __floats2half2_rn(z0, z1);
    *(__half2*)&g_z0[(size_t)b * XDIMv + j] = p;
}

// ============================================================
// GEMM: C[M,N] = act(A[M,K] @ W[K,N] + bias)
// A: single fp16 [M,K]; B: fp16 pair Wh/Wl [K,N].
// 2-term split: C += ah*bh + ah*bl   (A rounding error ~2^-12 rms)
// CTA 128x64, BK=32, 3-stage cp.async, padded smem, m16n8k16 fp16 MMA.
// ============================================================
#define BM 128
#define BN 64
#define BK 32
#define APITCH 40                      // halfs per A smem row (80 B)
#define BPITCH 72                      // halfs per B smem row (144 B)
#define A_BYTES (BM * APITCH * 2)      // 10240
#define B_BYTES (BK * BPITCH * 2)      //  4608 per half-array
#define STAGE_BYTES (A_BYTES + 2 * B_BYTES)   // 19456
#define STAGES 3
#define GEMM_SMEM_BYTES (STAGES * STAGE_BYTES) // 58368

template<int RELU>   // 1: fp16 out (next layer's A); 0: fp32 out
__global__ void __launch_bounds__(256, 2) k_gemm(
    const __half* __restrict__ A,
    const __half* __restrict__ Wh, const __half* __restrict__ Wl,
    const float* __restrict__ bias, void* __restrict__ outp,
    int M, int N, int K)
{
    extern __shared__ char smem[];
    const int tid  = threadIdx.x;
    const int lane = tid & 31;
    const int wid  = tid >> 5;
    const int wm   = wid & 3;        // 4 warps in M -> 32 rows each
    const int wn   = wid >> 2;       // 2 warps in N -> 32 cols each
    const int m0   = blockIdx.y * BM;
    const int n0   = blockIdx.x * BN;
    const int r    = lane >> 2;      // 0..7
    const int q    = lane & 3;       // 0..3

    float c[2][4][4];
#pragma unroll
    for (int i = 0; i < 2; i++)
#pragma unroll
        for (int j = 0; j < 4; j++)
#pragma unroll
            for (int k = 0; k < 4; k++) c[i][j][k] = 0.f;

    const int kIters = K / BK;

    auto loadStage = [&](int it, int stg) {
        const int k0 = it * BK;
        char* st = smem + stg * STAGE_BYTES;
        // A: 128 rows x 4 chunks of 16B = 512 chunks, 2 per thread
#pragma unroll
        for (int t = 0; t < 2; t++) {
            int id = tid + t * 256;
            int rr = id >> 2, ch = id & 3;
            const __half* src = A + (size_t)(m0 + rr) * K + k0 + ch * 8;
            cp16(st + rr * (APITCH * 2) + ch * 16, src);
        }
        // B: 2 arrays x 32 rows x 8 chunks of 16B = 512 chunks, 2 per thread
#pragma unroll
        for (int t = 0; t < 2; t++) {
            int id = tid + t * 256;
            int a  = id >> 8;
            int rb = id & 255;
            int rr = rb >> 3, ch = rb & 7;
            const __half* src = (a ? Wl : Wh) + (size_t)(k0 + rr) * N + n0 + ch * 8;
            cp16(st + A_BYTES + a * B_BYTES + rr * (BPITCH * 2) + ch * 16, src);
        }
    };

    loadStage(0, 0); CP_COMMIT();
    loadStage(1, 1); CP_COMMIT();

    for (int it = 0; it < kIters; ++it) {
        CP_WAIT1();
        __syncthreads();
        if (it + 2 < kIters) loadStage(it + 2, (it + 2) % STAGES);
        CP_COMMIT();

        const char* st  = smem + (it % STAGES) * STAGE_BYTES;
        const char* sA  = st;
        const char* sBh = st + A_BYTES;
        const char* sBl = st + A_BYTES + B_BYTES;

#pragma unroll
        for (int kk = 0; kk < BK; kk += 16) {
            uint32_t ah[2][4], bh[4][2], bl[4][2];
#pragma unroll
            for (int mt = 0; mt < 2; mt++) {
                const int ab = (wm * 32 + mt * 16 + r) * (APITCH * 2) + (kk + 2 * q) * 2;
                ah[mt][0] = *(const uint32_t*)(sA + ab);
                ah[mt][1] = *(const uint32_t*)(sA + ab + 8 * APITCH * 2);
                ah[mt][2] = *(const uint32_t*)(sA + ab + 16);
                ah[mt][3] = *(const uint32_t*)(sA + ab + 8 * APITCH * 2 + 16);
            }
#pragma unroll
            for (int nt = 0; nt < 4; nt++) {
                const int n  = wn * 32 + nt * 8 + r;
                const int kb = (kk + 2 * q) * (BPITCH * 2) + n * 2;
                uint32_t h00 = *(const uint16_t*)(sBh + kb);
                uint32_t h01 = *(const uint16_t*)(sBh + kb + BPITCH * 2);
                uint32_t h10 = *(const uint16_t*)(sBh + kb + 8 * BPITCH * 2);
                uint32_t h11 = *(const uint16_t*)(sBh + kb + 9 * BPITCH * 2);
                bh[nt][0] = merge16(h00, h01);
                bh[nt][1] = merge16(h10, h11);
                uint32_t l00 = *(const uint16_t*)(sBl + kb);
                uint32_t l01 = *(const uint16_t*)(sBl + kb + BPITCH * 2);
                uint32_t l10 = *(const uint16_t*)(sBl + kb + 8 * BPITCH * 2);
                uint32_t l11 = *(const uint16_t*)(sBl + kb + 9 * BPITCH * 2);
                bl[nt][0] = merge16(l00, l01);
                bl[nt][1] = merge16(l10, l11);
            }
            // 2 split terms; each sweep = 8 independent accumulators
#pragma unroll
            for (int mt = 0; mt < 2; mt++)
#pragma unroll
                for (int nt = 0; nt < 4; nt++)
                    MMA_F16(c[mt][nt], ah[mt], bh[nt]);
#pragma unroll
            for (int mt = 0; mt < 2; mt++)
#pragma unroll
                for (int nt = 0; nt < 4; nt++)
                    MMA_F16(c[mt][nt], ah[mt], bl[nt]);
        }
    }

    // ---------------- epilogue ----------------
#pragma unroll
    for (int mt = 0; mt < 2; mt++) {
#pragma unroll
        for (int nt = 0; nt < 4; nt++) {
            int row0 = m0 + wm * 32 + mt * 16 + r;
            int col0 = n0 + wn * 32 + nt * 8 + 2 * q;
            float bb0 = bias[col0], bb1 = bias[col0 + 1];
            float v00 = c[mt][nt][0] + bb0, v01 = c[mt][nt][1] + bb1;
            float v10 = c[mt][nt][2] + bb0, v11 = c[mt][nt][3] + bb1;
            if (RELU) {
                __half2 p0 = __floats2half2_rn(fmaxf(v00, 0.f), fmaxf(v01, 0.f));
                __half2 p1 = __floats2half2_rn(fmaxf(v10, 0.f), fmaxf(v11, 0.f));
                __half* z = (__half*)outp;
                *(__half2*)&z[(size_t)row0 * N + col0]       = p0;
                *(__half2*)&z[(size_t)(row0 + 8) * N + col0] = p1;
            } else {
                float* o = (float*)outp;
                *(float2*)&o[(size_t)row0 * N + col0]       = make_float2(v00, v01);
                *(float2*)&o[(size_t)(row0 + 8) * N + col0] = make_float2(v10, v11);
            }
        }
    }
}

// ============================================================
// launch
// ============================================================
extern "C" void kernel_launch(void* const* d_in, const int* in_sizes, int n_in,
                              void* d_out, int out_size) {
    const float* x  = (const float*)d_in[0];
    const int*   ei = (const int*)  d_in[1];
    const float* gw = (const float*)d_in[2];
    const float* gb = (const float*)d_in[3];
    const float* W1 = (const float*)d_in[4];
    const float* b1 = (const float*)d_in[5];
    const float* W2 = (const float*)d_in[6];
    const float* b2 = (const float*)d_in[7];
    const float* W3 = (const float*)d_in[8];
    const float* b3 = (const float*)d_in[9];
    float* out = (float*)d_out;

    cudaFuncSetAttribute(k_gemm<1>, cudaFuncAttributeMaxDynamicSharedMemorySize, GEMM_SMEM_BYTES);
    cudaFuncSetAttribute(k_gemm<0>, cudaFuncAttributeMaxDynamicSharedMemorySize, GEMM_SMEM_BYTES);

    void *z0p, *z1p, *z2p, *w1hp, *w1lp, *w2hp, *w2lp, *w3hp, *w3lp;
    cudaGetSymbolAddress(&z0p, g_z0);
    cudaGetSymbolAddress(&z1p, g_z1);
    cudaGetSymbolAddress(&z2p, g_z2);
    cudaGetSymbolAddress(&w1hp, g_w1h); cudaGetSymbolAddress(&w1lp, g_w1l);
    cudaGetSymbolAddress(&w2hp, g_w2h); cudaGetSymbolAddress(&w2lp, g_w2l);
    cudaGetSymbolAddress(&w3hp, g_w3h); cudaGetSymbolAddress(&w3lp, g_w3l);

    // fused init + weight split
    k_wsplit_all<<<(N1_4 + N2_4 + N3_4) / 256, 256>>>(W1, W2, W3);

    // GCN
    k_count<<<NEDGE / 256, 256>>>(ei);
    k_scatter<<<NEDGE / 256, 256>>>(ei, x, gw);
    k_build_z<<<dim3(XDIMv / 2 / 256, BATCH), 256>>>(x, gw, gb);

    // MLP
    dim3 g1(H1v / BN,   BATCH / BM);
    dim3 g2(H2v / BN,   BATCH / BM);
    dim3 g3(YDIMv / BN, BATCH / BM);
    k_gemm<1><<<g1, 256, GEMM_SMEM_BYTES>>>(
        (const __half*)z0p, (const __half*)w1hp, (const __half*)w1lp,
        b1, z1p, BATCH, H1v, XDIMv);
    k_gemm<1><<<g2, 256, GEMM_SMEM_BYTES>>>(
        (const __half*)z1p, (const __half*)w2hp, (const __half*)w2lp,
        b2, z2p, BATCH, H2v, H1v);
    k_gemm<0><<<g3, 256, GEMM_SMEM_BYTES>>>(
        (const __half*)z2p, (const __half*)w3hp, (const __half*)w3lp,
        b3, out, BATCH, YDIMv, H2v);
}

// round 10
// speedup vs baseline: 1.6041x; 1.1581x over previous
#include <cuda_runtime.h>
#include <cuda_fp16.h>
#include <cstdint>

// ---------------- problem constants ----------------
#define BATCH 512
#define NEQv  4096
#define XDIMv 6144
#define H1v   2048
#define H2v   2048
#define YDIMv 4096
#define NEDGE 32768

// ---------------- scratch (device globals; no runtime alloc) ----------------
__device__ __align__(256) __half g_z0[BATCH * XDIMv];   // fp16 activations
__device__ __align__(256) __half g_z1[BATCH * H1v];
__device__ __align__(256) __half g_z2[BATCH * H2v];
// weight pairs, k-pair-interleaved: Wp[(k/2)*N + n] = half2(W[k,n], W[k+1,n])
__device__ __align__(256) __half g_w1h[XDIMv * H1v];
__device__ __align__(256) __half g_w1l[XDIMv * H1v];
__device__ __align__(256) __half g_w2h[H1v * H2v];
__device__ __align__(256) __half g_w2l[H1v * H2v];
__device__ __align__(256) __half g_w3h[H2v * YDIMv];
__device__ __align__(256) __half g_w3l[H2v * YDIMv];
__device__ int   g_cnt[NEQv];
__device__ float g_acc[NEQv];

// ============================================================
// helpers
// ============================================================
__device__ __forceinline__ unsigned smem_u32(const void* p) {
    return (unsigned)__cvta_generic_to_shared(p);
}
__device__ __forceinline__ void cp16(void* dst, const void* src) {
    asm volatile("cp.async.ca.shared.global [%0], [%1], 16;\n"
                 :: "r"(smem_u32(dst)), "l"(src));
}
#define CP_COMMIT() asm volatile("cp.async.commit_group;\n")
#define CP_WAIT2()  asm volatile("cp.async.wait_group 2;\n")

#define MMA_F16(C, A, B)                                                         \
    asm volatile("mma.sync.aligned.m16n8k16.row.col.f32.f16.f16.f32 "            \
                 "{%0,%1,%2,%3},{%4,%5,%6,%7},{%8,%9},{%0,%1,%2,%3};\n"          \
                 : "+f"((C)[0]), "+f"((C)[1]), "+f"((C)[2]), "+f"((C)[3])         \
                 : "r"((A)[0]), "r"((A)[1]), "r"((A)[2]), "r"((A)[3]),            \
                   "r"((B)[0]), "r"((B)[1]))

// fp16 pair split: h = rn2(f0,f1), l = rn2(residuals)
__device__ __forceinline__ void hsplit2(float f0, float f1, uint32_t& h, uint32_t& l) {
    __half2 hh = __floats2half2_rn(f0, f1);
    float2 hf = __half22float2(hh);
    __half2 ll = __floats2half2_rn(f0 - hf.x, f1 - hf.y);
    h = *(uint32_t*)&hh;
    l = *(uint32_t*)&ll;
}

// ============================================================
// fused init + weight split into k-pair-interleaved fp16 layout.
// thread j of a matrix handles pair-row kp = j/(N/4), col-quad nb = j%(N/4):
// reads W[2kp][4n], W[2kp+1][4n]; writes 4 interleaved half2 to Wh/Wl.
// ============================================================
#define N1_8 (XDIMv * H1v / 8)
#define N2_8 (H1v * H2v / 8)
#define N3_8 (H2v * YDIMv / 8)

__device__ __forceinline__ void wsplit_one(const float* __restrict__ W,
                                           __half* __restrict__ Wh, __half* __restrict__ Wl,
                                           int j, int n4shift) {
    const int n4mask = (1 << n4shift) - 1;
    int kp = j >> n4shift;
    int nb = j & n4mask;
    const float4* Wv = (const float4*)W;
    float4 r0 = Wv[((size_t)(2 * kp) << n4shift) + nb];
    float4 r1 = Wv[((size_t)(2 * kp + 1) << n4shift) + nb];
    uint4 h, l;
    hsplit2(r0.x, r1.x, h.x, l.x);
    hsplit2(r0.y, r1.y, h.y, l.y);
    hsplit2(r0.z, r1.z, h.z, l.z);
    hsplit2(r0.w, r1.w, h.w, l.w);
    ((uint4*)Wh)[j] = h;
    ((uint4*)Wl)[j] = l;
}

__global__ void k_wsplit_all(const float* __restrict__ W1, const float* __restrict__ W2,
                             const float* __restrict__ W3) {
    int i = blockIdx.x * blockDim.x + threadIdx.x;
    if (i < NEQv) { g_cnt[i] = 0; g_acc[i] = 0.f; }
    if (i < N1_8) {
        wsplit_one(W1, g_w1h, g_w1l, i, 9);                    // N=2048, N/4=512
    } else if (i < N1_8 + N2_8) {
        wsplit_one(W2, g_w2h, g_w2l, i - N1_8, 9);             // N=2048
    } else {
        wsplit_one(W3, g_w3h, g_w3l, i - (N1_8 + N2_8), 10);   // N=4096, N/4=1024
    }
}

// ============================================================
// GCN kernels
// ============================================================
__global__ void k_count(const int* __restrict__ ei) {
    int e = blockIdx.x * blockDim.x + threadIdx.x;
    if (e < NEDGE) atomicAdd(&g_cnt[ei[NEDGE + e]], 1);
}
__global__ void k_scatter(const int* __restrict__ ei, const float* __restrict__ x,
                          const float* __restrict__ gw) {
    int e = blockIdx.x * blockDim.x + threadIdx.x;
    if (e >= NEDGE) return;
    int s = ei[e];
    int d = ei[NEDGE + e];
    float deg_s = 1.f + 512.f * (float)g_cnt[s];
    float xw = gw[0] * x[(size_t)(s & 511) * XDIMv + (s >> 9)];
    atomicAdd(&g_acc[d], rsqrtf(deg_s) * xw);
}
__global__ void k_build_z(const float* __restrict__ x, const float* __restrict__ gw,
                          const float* __restrict__ gb) {
    int j = (blockIdx.x * blockDim.x + threadIdx.x) * 2;
    int b = blockIdx.y;
    float2 v = *(const float2*)&x[(size_t)b * XDIMv + j];
    float z0, z1;
    if (j >= NEQv) {
        z0 = v.x; z1 = v.y;
    } else {
        float w = gw[0], bb = gb[0];
        float xw0 = w * v.x, xw1 = w * v.y;
        float o0, o1;
        if (j < 8) {
            int i0 = (j << 9) + b;
            float deg0 = 1.f + 512.f * (float)g_cnt[i0];
            o0 = xw0 / deg0 + 512.f * rsqrtf(deg0) * g_acc[i0] + bb;
            if (j + 1 < 8) {
                int i1 = ((j + 1) << 9) + b;
                float deg1 = 1.f + 512.f * (float)g_cnt[i1];
                o1 = xw1 / deg1 + 512.f * rsqrtf(deg1) * g_acc[i1] + bb;
            } else {
                o1 = xw1 + bb;
            }
        } else {
            o0 = xw0 + bb;
            o1 = xw1 + bb;
        }
        z0 = fmaxf(o0, 0.f);
        z1 = fmaxf(o1, 0.f);
    }
    __half2 p = __floats2half2_rn(z0, z1);
    *(__half2*)&g_z0[(size_t)b * XDIMv + j] = p;
}

// ============================================================
// GEMM: C[M,N] = act(A[M,K] @ W[K,N] + bias)
// A: fp16 [M,K];  B: fp16 pairs, k-pair-interleaved [(K/2) x N] half2.
// B fragments = single LDS.32 each (no merges). 2-term split MMA.
// CTA 128x64, BK=32, 4-stage cp.async.
// ============================================================
#define BM 128
#define BN 64
#define BK 32
#define APITCH 40                      // halfs per A smem row (80 B)
#define BPITCH32 72                    // uint32 per B smem row (288 B); 72%32=8 -> conflict-free
#define A_BYTES (BM * APITCH * 2)      // 10240
#define B_BYTES (16 * BPITCH32 * 4)    // 4608 per array (16 pair-rows)
#define STAGE_BYTES (A_BYTES + 2 * B_BYTES)    // 19456
#define STAGES 4
#define GEMM_SMEM_BYTES (STAGES * STAGE_BYTES) // 77824

template<int RELU>   // 1: fp16 out (next layer's A); 0: fp32 out
__global__ void __launch_bounds__(256, 2) k_gemm(
    const __half* __restrict__ A,
    const __half* __restrict__ Wh, const __half* __restrict__ Wl,
    const float* __restrict__ bias, void* __restrict__ outp,
    int M, int N, int K)
{
    extern __shared__ char smem[];
    const int tid  = threadIdx.x;
    const int lane = tid & 31;
    const int wid  = tid >> 5;
    const int wm   = wid & 3;        // 4 warps in M -> 32 rows each
    const int wn   = wid >> 2;       // 2 warps in N -> 32 cols each
    const int m0   = blockIdx.y * BM;
    const int n0   = blockIdx.x * BN;
    const int r    = lane >> 2;      // 0..7
    const int q    = lane & 3;       // 0..3

    float c[2][4][4];
#pragma unroll
    for (int i = 0; i < 2; i++)
#pragma unroll
        for (int j = 0; j < 4; j++)
#pragma unroll
            for (int k = 0; k < 4; k++) c[i][j][k] = 0.f;

    const int kIters = K / BK;
    const uint32_t* Whp = (const uint32_t*)Wh;
    const uint32_t* Wlp = (const uint32_t*)Wl;

    auto loadStage = [&](int it, int stg) {
        const int k0 = it * BK;
        char* st = smem + stg * STAGE_BYTES;
        // A: 128 rows x 4 chunks of 16B = 512 chunks, 2 per thread
#pragma unroll
        for (int t = 0; t < 2; t++) {
            int id = tid + t * 256;
            int rr = id >> 2, ch = id & 3;
            const __half* src = A + (size_t)(m0 + rr) * K + k0 + ch * 8;
            cp16(st + rr * (APITCH * 2) + ch * 16, src);
        }
        // B: 2 arrays x 16 pair-rows x 16 chunks of 16B = 512 chunks, 2 per thread
#pragma unroll
        for (int t = 0; t < 2; t++) {
            int id = tid + t * 256;
            int a  = id >> 8;
            int rb = id & 255;
            int rr = rb >> 4, ch = rb & 15;
            const uint32_t* src = (a ? Wlp : Whp) + (size_t)(k0 / 2 + rr) * N + n0 + ch * 4;
            cp16(st + A_BYTES + a * B_BYTES + rr * (BPITCH32 * 4) + ch * 16, src);
        }
    };

    loadStage(0, 0); CP_COMMIT();
    loadStage(1, 1); CP_COMMIT();
    loadStage(2, 2); CP_COMMIT();

    for (int it = 0; it < kIters; ++it) {
        CP_WAIT2();
        __syncthreads();
        if (it + 3 < kIters) loadStage(it + 3, (it + 3) & 3);
        CP_COMMIT();

        const char* st  = smem + (it & 3) * STAGE_BYTES;
        const char* sA  = st;
        const uint32_t* sBh = (const uint32_t*)(st + A_BYTES);
        const uint32_t* sBl = (const uint32_t*)(st + A_BYTES + B_BYTES);

#pragma unroll
        for (int kk = 0; kk < BK; kk += 16) {
            uint32_t ah[2][4], bh[4][2], bl[4][2];
#pragma unroll
            for (int mt = 0; mt < 2; mt++) {
                const int ab = (wm * 32 + mt * 16 + r) * (APITCH * 2) + (kk + 2 * q) * 2;
                ah[mt][0] = *(const uint32_t*)(sA + ab);
                ah[mt][1] = *(const uint32_t*)(sA + ab + 8 * APITCH * 2);
                ah[mt][2] = *(const uint32_t*)(sA + ab + 16);
                ah[mt][3] = *(const uint32_t*)(sA + ab + 8 * APITCH * 2 + 16);
            }
            const int p0 = (kk >> 1) + q;                 // pair row
#pragma unroll
            for (int nt = 0; nt < 4; nt++) {
                const int n   = wn * 32 + nt * 8 + r;
                const int i0  = p0 * BPITCH32 + n;
                bh[nt][0] = sBh[i0];
                bh[nt][1] = sBh[i0 + 4 * BPITCH32];
                bl[nt][0] = sBl[i0];
                bl[nt][1] = sBl[i0 + 4 * BPITCH32];
            }
            // 2 split terms; each sweep = 8 independent accumulators
#pragma unroll
            for (int mt = 0; mt < 2; mt++)
#pragma unroll
                for (int nt = 0; nt < 4; nt++)
                    MMA_F16(c[mt][nt], ah[mt], bh[nt]);
#pragma unroll
            for (int mt = 0; mt < 2; mt++)
#pragma unroll
                for (int nt = 0; nt < 4; nt++)
                    MMA_F16(c[mt][nt], ah[mt], bl[nt]);
        }
    }

    // ---------------- epilogue ----------------
#pragma unroll
    for (int mt = 0; mt < 2; mt++) {
#pragma unroll
        for (int nt = 0; nt < 4; nt++) {
            int row0 = m0 + wm * 32 + mt * 16 + r;
            int col0 = n0 + wn * 32 + nt * 8 + 2 * q;
            float bb0 = bias[col0], bb1 = bias[col0 + 1];
            float v00 = c[mt][nt][0] + bb0, v01 = c[mt][nt][1] + bb1;
            float v10 = c[mt][nt][2] + bb0, v11 = c[mt][nt][3] + bb1;
            if (RELU) {
                __half2 p0 = __floats2half2_rn(fmaxf(v00, 0.f), fmaxf(v01, 0.f));
                __half2 p1 = __floats2half2_rn(fmaxf(v10, 0.f), fmaxf(v11, 0.f));
                __half* z = (__half*)outp;
                *(__half2*)&z[(size_t)row0 * N + col0]       = p0;
                *(__half2*)&z[(size_t)(row0 + 8) * N + col0] = p1;
            } else {
                float* o = (float*)outp;
                *(float2*)&o[(size_t)row0 * N + col0]       = make_float2(v00, v01);
                *(float2*)&o[(size_t)(row0 + 8) * N + col0] = make_float2(v10, v11);
            }
        }
    }
}

// ============================================================
// launch
// ============================================================
extern "C" void kernel_launch(void* const* d_in, const int* in_sizes, int n_in,
                              void* d_out, int out_size) {
    const float* x  = (const float*)d_in[0];
    const int*   ei = (const int*)  d_in[1];
    const float* gw = (const float*)d_in[2];
    const float* gb = (const float*)d_in[3];
    const float* W1 = (const float*)d_in[4];
    const float* b1 = (const float*)d_in[5];
    const float* W2 = (const float*)d_in[6];
    const float* b2 = (const float*)d_in[7];
    const float* W3 = (const float*)d_in[8];
    const float* b3 = (const float*)d_in[9];
    float* out = (float*)d_out;

    cudaFuncSetAttribute(k_gemm<1>, cudaFuncAttributeMaxDynamicSharedMemorySize, GEMM_SMEM_BYTES);
    cudaFuncSetAttribute(k_gemm<0>, cudaFuncAttributeMaxDynamicSharedMemorySize, GEMM_SMEM_BYTES);

    void *z0p, *z1p, *z2p, *w1hp, *w1lp, *w2hp, *w2lp, *w3hp, *w3lp;
    cudaGetSymbolAddress(&z0p, g_z0);
    cudaGetSymbolAddress(&z1p, g_z1);
    cudaGetSymbolAddress(&z2p, g_z2);
    cudaGetSymbolAddress(&w1hp, g_w1h); cudaGetSymbolAddress(&w1lp, g_w1l);
    cudaGetSymbolAddress(&w2hp, g_w2h); cudaGetSymbolAddress(&w2lp, g_w2l);
    cudaGetSymbolAddress(&w3hp, g_w3h); cudaGetSymbolAddress(&w3lp, g_w3l);

    // fused init + weight split (k-pair-interleaved)
    k_wsplit_all<<<(N1_8 + N2_8 + N3_8) / 256, 256>>>(W1, W2, W3);

    // GCN
    k_count<<<NEDGE / 256, 256>>>(ei);
    k_scatter<<<NEDGE / 256, 256>>>(ei, x, gw);
    k_build_z<<<dim3(XDIMv / 2 / 256, BATCH), 256>>>(x, gw, gb);

    // MLP
    dim3 g1(H1v / BN,   BATCH / BM);
    dim3 g2(H2v / BN,   BATCH / BM);
    dim3 g3(YDIMv / BN, BATCH / BM);
    k_gemm<1><<<g1, 256, GEMM_SMEM_BYTES>>>(
        (const __half*)z0p, (const __half*)w1hp, (const __half*)w1lp,
        b1, z1p, BATCH, H1v, XDIMv);
    k_gemm<1><<<g2, 256, GEMM_SMEM_BYTES>>>(
        (const __half*)z1p, (const __half*)w2hp, (const __half*)w2lp,
        b2, z2p, BATCH, H2v, H1v);
    k_gemm<0><<<g3, 256, GEMM_SMEM_BYTES>>>(
        (const __half*)z2p, (const __half*)w3hp, (const __half*)w3lp,
        b3, out, BATCH, YDIMv, H2v);
}

// round 11
// speedup vs baseline: 2.2016x; 1.3725x over previous
#include <cuda_runtime.h>
#include <cuda_fp16.h>
#include <cstdint>

// ---------------- problem constants ----------------
#define BATCH 512
#define NEQv  4096
#define XDIMv 6144
#define H1v   2048
#define H2v   2048
#define YDIMv 4096
#define NEDGE 32768

// ---------------- scratch (device globals; no runtime alloc) ----------------
__device__ __align__(256) __half g_z0[BATCH * XDIMv];   // fp16 activations
__device__ __align__(256) __half g_z1[BATCH * H1v];
__device__ __align__(256) __half g_z2[BATCH * H2v];
// weights fp16, k-pair-interleaved: Wp[(k/2)*N + n] = half2(W[k,n], W[k+1,n])
__device__ __align__(256) __half g_w1[XDIMv * H1v];
__device__ __align__(256) __half g_w2[H1v * H2v];
__device__ __align__(256) __half g_w3[H2v * YDIMv];
__device__ int   g_cnt[NEQv];
__device__ float g_acc[NEQv];

// ============================================================
// helpers
// ============================================================
__device__ __forceinline__ unsigned smem_u32(const void* p) {
    return (unsigned)__cvta_generic_to_shared(p);
}
__device__ __forceinline__ void cp16(void* dst, const void* src) {
    asm volatile("cp.async.ca.shared.global [%0], [%1], 16;\n"
                 :: "r"(smem_u32(dst)), "l"(src));
}
#define CP_COMMIT() asm volatile("cp.async.commit_group;\n")
#define CP_WAIT2()  asm volatile("cp.async.wait_group 2;\n")

#define MMA_F16(C, A, B)                                                         \
    asm volatile("mma.sync.aligned.m16n8k16.row.col.f32.f16.f16.f32 "            \
                 "{%0,%1,%2,%3},{%4,%5,%6,%7},{%8,%9},{%0,%1,%2,%3};\n"          \
                 : "+f"((C)[0]), "+f"((C)[1]), "+f"((C)[2]), "+f"((C)[3])         \
                 : "r"((A)[0]), "r"((A)[1]), "r"((A)[2]), "r"((A)[3]),            \
                   "r"((B)[0]), "r"((B)[1]))

// ============================================================
// fused init + weight convert into k-pair-interleaved fp16 layout.
// thread j: pair-row kp = j >> n4shift, col-quad nb = j & mask;
// reads W[2kp][4n..], W[2kp+1][4n..]; writes 4 interleaved half2.
// ============================================================
#define N1_8 (XDIMv * H1v / 8)
#define N2_8 (H1v * H2v / 8)
#define N3_8 (H2v * YDIMv / 8)

__device__ __forceinline__ void wconv_one(const float* __restrict__ W,
                                          __half* __restrict__ Wp,
                                          int j, int n4shift) {
    const int n4mask = (1 << n4shift) - 1;
    int kp = j >> n4shift;
    int nb = j & n4mask;
    const float4* Wv = (const float4*)W;
    float4 r0 = Wv[((size_t)(2 * kp) << n4shift) + nb];
    float4 r1 = Wv[((size_t)(2 * kp + 1) << n4shift) + nb];
    __half2 h0 = __floats2half2_rn(r0.x, r1.x);
    __half2 h1 = __floats2half2_rn(r0.y, r1.y);
    __half2 h2 = __floats2half2_rn(r0.z, r1.z);
    __half2 h3 = __floats2half2_rn(r0.w, r1.w);
    uint4 h;
    h.x = *(uint32_t*)&h0; h.y = *(uint32_t*)&h1;
    h.z = *(uint32_t*)&h2; h.w = *(uint32_t*)&h3;
    ((uint4*)Wp)[j] = h;
}

__global__ void k_wconv_all(const float* __restrict__ W1, const float* __restrict__ W2,
                            const float* __restrict__ W3) {
    int i = blockIdx.x * blockDim.x + threadIdx.x;
    if (i < NEQv) { g_cnt[i] = 0; g_acc[i] = 0.f; }
    if (i < N1_8) {
        wconv_one(W1, g_w1, i, 9);                    // N=2048, N/4=512
    } else if (i < N1_8 + N2_8) {
        wconv_one(W2, g_w2, i - N1_8, 9);             // N=2048
    } else {
        wconv_one(W3, g_w3, i - (N1_8 + N2_8), 10);   // N=4096, N/4=1024
    }
}

// ============================================================
// GCN kernels
// ============================================================
__global__ void k_count(const int* __restrict__ ei) {
    int e = blockIdx.x * blockDim.x + threadIdx.x;
    if (e < NEDGE) atomicAdd(&g_cnt[ei[NEDGE + e]], 1);
}
__global__ void k_scatter(const int* __restrict__ ei, const float* __restrict__ x,
                          const float* __restrict__ gw) {
    int e = blockIdx.x * blockDim.x + threadIdx.x;
    if (e >= NEDGE) return;
    int s = ei[e];
    int d = ei[NEDGE + e];
    float deg_s = 1.f + 512.f * (float)g_cnt[s];
    float xw = gw[0] * x[(size_t)(s & 511) * XDIMv + (s >> 9)];
    atomicAdd(&g_acc[d], rsqrtf(deg_s) * xw);
}
__global__ void k_build_z(const float* __restrict__ x, const float* __restrict__ gw,
                          const float* __restrict__ gb) {
    int j = (blockIdx.x * blockDim.x + threadIdx.x) * 2;
    int b = blockIdx.y;
    float2 v = *(const float2*)&x[(size_t)b * XDIMv + j];
    float z0, z1;
    if (j >= NEQv) {
        z0 = v.x; z1 = v.y;
    } else {
        float w = gw[0], bb = gb[0];
        float xw0 = w * v.x, xw1 = w * v.y;
        float o0, o1;
        if (j < 8) {
            int i0 = (j << 9) + b;
            float deg0 = 1.f + 512.f * (float)g_cnt[i0];
            o0 = xw0 / deg0 + 512.f * rsqrtf(deg0) * g_acc[i0] + bb;
            if (j + 1 < 8) {
                int i1 = ((j + 1) << 9) + b;
                float deg1 = 1.f + 512.f * (float)g_cnt[i1];
                o1 = xw1 / deg1 + 512.f * rsqrtf(deg1) * g_acc[i1] + bb;
            } else {
                o1 = xw1 + bb;
            }
        } else {
            o0 = xw0 + bb;
            o1 = xw1 + bb;
        }
        z0 = fmaxf(o0, 0.f);
        z1 = fmaxf(o1, 0.f);
    }
    __half2 p = __floats2half2_rn(z0, z1);
    *(__half2*)&g_z0[(size_t)b * XDIMv + j] = p;
}

// ============================================================
// GEMM: C[M,N] = act(A[M,K] @ W[K,N] + bias)
// A: fp16 [M,K];  B: fp16 k-pair-interleaved [(K/2) x N] half2.
// Pure fp16 MMA (fp32 accumulate), single term.
// CTA 128x64, BK=32, 4-stage cp.async, padded smem.
// ============================================================
#define BM 128
#define BN 64
#define BK 32
#define APITCH 40                      // halfs per A smem row (80 B)
#define BPITCH32 72                    // uint32 per B smem row (288 B); 72%32=8 -> conflict-free
#define A_BYTES (BM * APITCH * 2)      // 10240
#define B_BYTES (16 * BPITCH32 * 4)    // 4608 (16 pair-rows)
#define STAGE_BYTES (A_BYTES + B_BYTES)        // 14848
#define STAGES 4
#define GEMM_SMEM_BYTES (STAGES * STAGE_BYTES) // 59392

template<int RELU>   // 1: fp16 out (next layer's A); 0: fp32 out
__global__ void __launch_bounds__(256, 2) k_gemm(
    const __half* __restrict__ A, const __half* __restrict__ W,
    const float* __restrict__ bias, void* __restrict__ outp,
    int M, int N, int K)
{
    extern __shared__ char smem[];
    const int tid  = threadIdx.x;
    const int lane = tid & 31;
    const int wid  = tid >> 5;
    const int wm   = wid & 3;        // 4 warps in M -> 32 rows each
    const int wn   = wid >> 2;       // 2 warps in N -> 32 cols each
    const int m0   = blockIdx.y * BM;
    const int n0   = blockIdx.x * BN;
    const int r    = lane >> 2;      // 0..7
    const int q    = lane & 3;       // 0..3

    float c[2][4][4];
#pragma unroll
    for (int i = 0; i < 2; i++)
#pragma unroll
        for (int j = 0; j < 4; j++)
#pragma unroll
            for (int k = 0; k < 4; k++) c[i][j][k] = 0.f;

    const int kIters = K / BK;
    const uint32_t* Wp = (const uint32_t*)W;

    auto loadStage = [&](int it, int stg) {
        const int k0 = it * BK;
        char* st = smem + stg * STAGE_BYTES;
        // A: 128 rows x 4 chunks of 16B = 512 chunks, 2 per thread
#pragma unroll
        for (int t = 0; t < 2; t++) {
            int id = tid + t * 256;
            int rr = id >> 2, ch = id & 3;
            const __half* src = A + (size_t)(m0 + rr) * K + k0 + ch * 8;
            cp16(st + rr * (APITCH * 2) + ch * 16, src);
        }
        // B: 16 pair-rows x 16 chunks of 16B = 256 chunks, 1 per thread
        {
            int rr = tid >> 4, ch = tid & 15;
            const uint32_t* src = Wp + (size_t)(k0 / 2 + rr) * N + n0 + ch * 4;
            cp16(st + A_BYTES + rr * (BPITCH32 * 4) + ch * 16, src);
        }
    };

    loadStage(0, 0); CP_COMMIT();
    loadStage(1, 1); CP_COMMIT();
    loadStage(2, 2); CP_COMMIT();

    for (int it = 0; it < kIters; ++it) {
        CP_WAIT2();
        __syncthreads();
        if (it + 3 < kIters) loadStage(it + 3, (it + 3) & 3);
        CP_COMMIT();

        const char* st  = smem + (it & 3) * STAGE_BYTES;
        const char* sA  = st;
        const uint32_t* sB = (const uint32_t*)(st + A_BYTES);

#pragma unroll
        for (int kk = 0; kk < BK; kk += 16) {
            uint32_t ah[2][4], bh[4][2];
#pragma unroll
            for (int mt = 0; mt < 2; mt++) {
                const int ab = (wm * 32 + mt * 16 + r) * (APITCH * 2) + (kk + 2 * q) * 2;
                ah[mt][0] = *(const uint32_t*)(sA + ab);
                ah[mt][1] = *(const uint32_t*)(sA + ab + 8 * APITCH * 2);
                ah[mt][2] = *(const uint32_t*)(sA + ab + 16);
                ah[mt][3] = *(const uint32_t*)(sA + ab + 8 * APITCH * 2 + 16);
            }
            const int p0 = (kk >> 1) + q;                 // pair row
#pragma unroll
            for (int nt = 0; nt < 4; nt++) {
                const int n  = wn * 32 + nt * 8 + r;
                const int i0 = p0 * BPITCH32 + n;
                bh[nt][0] = sB[i0];
                bh[nt][1] = sB[i0 + 4 * BPITCH32];
            }
            // 8 independent accumulators
#pragma unroll
            for (int mt = 0; mt < 2; mt++)
#pragma unroll
                for (int nt = 0; nt < 4; nt++)
                    MMA_F16(c[mt][nt], ah[mt], bh[nt]);
        }
    }

    // ---------------- epilogue ----------------
#pragma unroll
    for (int mt = 0; mt < 2; mt++) {
#pragma unroll
        for (int nt = 0; nt < 4; nt++) {
            int row0 = m0 + wm * 32 + mt * 16 + r;
            int col0 = n0 + wn * 32 + nt * 8 + 2 * q;
            float bb0 = bias[col0], bb1 = bias[col0 + 1];
            float v00 = c[mt][nt][0] + bb0, v01 = c[mt][nt][1] + bb1;
            float v10 = c[mt][nt][2] + bb0, v11 = c[mt][nt][3] + bb1;
            if (RELU) {
                __half2 p0 = __floats2half2_rn(fmaxf(v00, 0.f), fmaxf(v01, 0.f));
                __half2 p1 = __floats2half2_rn(fmaxf(v10, 0.f), fmaxf(v11, 0.f));
                __half* z = (__half*)outp;
                *(__half2*)&z[(size_t)row0 * N + col0]       = p0;
                *(__half2*)&z[(size_t)(row0 + 8) * N + col0] = p1;
            } else {
                float* o = (float*)outp;
                *(float2*)&o[(size_t)row0 * N + col0]       = make_float2(v00, v01);
                *(float2*)&o[(size_t)(row0 + 8) * N + col0] = make_float2(v10, v11);
            }
        }
    }
}

// ============================================================
// launch
// ============================================================
extern "C" void kernel_launch(void* const* d_in, const int* in_sizes, int n_in,
                              void* d_out, int out_size) {
    const float* x  = (const float*)d_in[0];
    const int*   ei = (const int*)  d_in[1];
    const float* gw = (const float*)d_in[2];
    const float* gb = (const float*)d_in[3];
    const float* W1 = (const float*)d_in[4];
    const float* b1 = (const float*)d_in[5];
    const float* W2 = (const float*)d_in[6];
    const float* b2 = (const float*)d_in[7];
    const float* W3 = (const float*)d_in[8];
    const float* b3 = (const float*)d_in[9];
    float* out = (float*)d_out;

    cudaFuncSetAttribute(k_gemm<1>, cudaFuncAttributeMaxDynamicSharedMemorySize, GEMM_SMEM_BYTES);
    cudaFuncSetAttribute(k_gemm<0>, cudaFuncAttributeMaxDynamicSharedMemorySize, GEMM_SMEM_BYTES);

    void *z0p, *z1p, *z2p, *w1p, *w2p, *w3p;
    cudaGetSymbolAddress(&z0p, g_z0);
    cudaGetSymbolAddress(&z1p, g_z1);
    cudaGetSymbolAddress(&z2p, g_z2);
    cudaGetSymbolAddress(&w1p, g_w1);
    cudaGetSymbolAddress(&w2p, g_w2);
    cudaGetSymbolAddress(&w3p, g_w3);

    // fused init + weight convert (k-pair-interleaved fp16)
    k_wconv_all<<<(N1_8 + N2_8 + N3_8) / 256, 256>>>(W1, W2, W3);

    // GCN
    k_count<<<NEDGE / 256, 256>>>(ei);
    k_scatter<<<NEDGE / 256, 256>>>(ei, x, gw);
    k_build_z<<<dim3(XDIMv / 2 / 256, BATCH), 256>>>(x, gw, gb);

    // MLP
    dim3 g1(H1v / BN,   BATCH / BM);
    dim3 g2(H2v / BN,   BATCH / BM);
    dim3 g3(YDIMv / BN, BATCH / BM);
    k_gemm<1><<<g1, 256, GEMM_SMEM_BYTES>>>(
        (const __half*)z0p, (const __half*)w1p, b1, z1p, BATCH, H1v, XDIMv);
    k_gemm<1><<<g2, 256, GEMM_SMEM_BYTES>>>(
        (const __half*)z1p, (const __half*)w2p, b2, z2p, BATCH, H2v, H1v);
    k_gemm<0><<<g3, 256, GEMM_SMEM_BYTES>>>(
        (const __half*)z2p, (const __half*)w3p, b3, out, BATCH, YDIMv, H2v);
}

// round 12
// speedup vs baseline: 2.5093x; 1.1398x over previous
#include <cuda_runtime.h>
#include <cuda_fp16.h>
#include <cstdint>

// ---------------- problem constants ----------------
#define BATCH 512
#define NEQv  4096
#define XDIMv 6144
#define H1v   2048
#define H2v   2048
#define YDIMv 4096
#define NEDGE 32768

// ---------------- scratch (device globals; no runtime alloc) ----------------
__device__ __align__(256) __half g_z0[BATCH * XDIMv];   // fp16 activations
__device__ __align__(256) __half g_z1[BATCH * H1v];
__device__ __align__(256) __half g_z2[BATCH * H2v];
// weights fp16, k-pair-interleaved: Wp[(k/2)*N + n] = half2(W[k,n], W[k+1,n])
__device__ __align__(256) __half g_w1[XDIMv * H1v];
__device__ __align__(256) __half g_w2[H1v * H2v];
__device__ __align__(256) __half g_w3[H2v * YDIMv];
__device__ int   g_cnt[NEQv];
__device__ float g_acc[NEQv];

// ============================================================
// helpers
// ============================================================
__device__ __forceinline__ unsigned smem_u32(const void* p) {
    return (unsigned)__cvta_generic_to_shared(p);
}
__device__ __forceinline__ void cp16(void* dst, const void* src) {
    asm volatile("cp.async.ca.shared.global [%0], [%1], 16;\n"
                 :: "r"(smem_u32(dst)), "l"(src));
}
#define CP_COMMIT() asm volatile("cp.async.commit_group;\n")
#define CP_WAIT1()  asm volatile("cp.async.wait_group 1;\n")

#define MMA_F16(C, A, B)                                                         \
    asm volatile("mma.sync.aligned.m16n8k16.row.col.f32.f16.f16.f32 "            \
                 "{%0,%1,%2,%3},{%4,%5,%6,%7},{%8,%9},{%0,%1,%2,%3};\n"          \
                 : "+f"((C)[0]), "+f"((C)[1]), "+f"((C)[2]), "+f"((C)[3])         \
                 : "r"((A)[0]), "r"((A)[1]), "r"((A)[2]), "r"((A)[3]),            \
                   "r"((B)[0]), "r"((B)[1]))

#define LDSM_X4(R, ADDR)                                                         \
    asm volatile("ldmatrix.sync.aligned.m8n8.x4.shared.b16 {%0,%1,%2,%3}, [%4];" \
                 : "=r"((R)[0]), "=r"((R)[1]), "=r"((R)[2]), "=r"((R)[3])        \
                 : "r"(ADDR))

// ============================================================
// fused init + weight convert into k-pair-interleaved fp16 layout (R11-proven)
// ============================================================
#define N1_8 (XDIMv * H1v / 8)
#define N2_8 (H1v * H2v / 8)
#define N3_8 (H2v * YDIMv / 8)

__device__ __forceinline__ void wconv_one(const float* __restrict__ W,
                                          __half* __restrict__ Wp,
                                          int j, int n4shift) {
    const int n4mask = (1 << n4shift) - 1;
    int kp = j >> n4shift;
    int nb = j & n4mask;
    const float4* Wv = (const float4*)W;
    float4 r0 = Wv[((size_t)(2 * kp) << n4shift) + nb];
    float4 r1 = Wv[((size_t)(2 * kp + 1) << n4shift) + nb];
    __half2 h0 = __floats2half2_rn(r0.x, r1.x);
    __half2 h1 = __floats2half2_rn(r0.y, r1.y);
    __half2 h2 = __floats2half2_rn(r0.z, r1.z);
    __half2 h3 = __floats2half2_rn(r0.w, r1.w);
    uint4 h;
    h.x = *(uint32_t*)&h0; h.y = *(uint32_t*)&h1;
    h.z = *(uint32_t*)&h2; h.w = *(uint32_t*)&h3;
    ((uint4*)Wp)[j] = h;
}

__global__ void k_wconv_all(const float* __restrict__ W1, const float* __restrict__ W2,
                            const float* __restrict__ W3) {
    int i = blockIdx.x * blockDim.x + threadIdx.x;
    if (i < NEQv) { g_cnt[i] = 0; g_acc[i] = 0.f; }
    if (i < N1_8) {
        wconv_one(W1, g_w1, i, 9);
    } else if (i < N1_8 + N2_8) {
        wconv_one(W2, g_w2, i - N1_8, 9);
    } else {
        wconv_one(W3, g_w3, i - (N1_8 + N2_8), 10);
    }
}

// ============================================================
// GCN kernels (proven)
// ============================================================
__global__ void k_count(const int* __restrict__ ei) {
    int e = blockIdx.x * blockDim.x + threadIdx.x;
    if (e < NEDGE) atomicAdd(&g_cnt[ei[NEDGE + e]], 1);
}
__global__ void k_scatter(const int* __restrict__ ei, const float* __restrict__ x,
                          const float* __restrict__ gw) {
    int e = blockIdx.x * blockDim.x + threadIdx.x;
    if (e >= NEDGE) return;
    int s = ei[e];
    int d = ei[NEDGE + e];
    float deg_s = 1.f + 512.f * (float)g_cnt[s];
    float xw = gw[0] * x[(size_t)(s & 511) * XDIMv + (s >> 9)];
    atomicAdd(&g_acc[d], rsqrtf(deg_s) * xw);
}
__global__ void k_build_z(const float* __restrict__ x, const float* __restrict__ gw,
                          const float* __restrict__ gb) {
    int j = (blockIdx.x * blockDim.x + threadIdx.x) * 2;
    int b = blockIdx.y;
    float2 v = *(const float2*)&x[(size_t)b * XDIMv + j];
    float z0, z1;
    if (j >= NEQv) {
        z0 = v.x; z1 = v.y;
    } else {
        float w = gw[0], bb = gb[0];
        float xw0 = w * v.x, xw1 = w * v.y;
        float o0, o1;
        if (j < 8) {
            int i0 = (j << 9) + b;
            float deg0 = 1.f + 512.f * (float)g_cnt[i0];
            o0 = xw0 / deg0 + 512.f * rsqrtf(deg0) * g_acc[i0] + bb;
            if (j + 1 < 8) {
                int i1 = ((j + 1) << 9) + b;
                float deg1 = 1.f + 512.f * (float)g_cnt[i1];
                o1 = xw1 / deg1 + 512.f * rsqrtf(deg1) * g_acc[i1] + bb;
            } else {
                o1 = xw1 + bb;
            }
        } else {
            o0 = xw0 + bb;
            o1 = xw1 + bb;
        }
        z0 = fmaxf(o0, 0.f);
        z1 = fmaxf(o1, 0.f);
    }
    __half2 p = __floats2half2_rn(z0, z1);
    *(__half2*)&g_z0[(size_t)b * XDIMv + j] = p;
}

// ============================================================
// GEMM: C[M,N] = act(A[M,K] @ W[K,N] + bias)
// A: fp16 [M,K] -> padded smem rows -> ldmatrix.x4 fragments (conflict-free)
// B: fp16 k-pair-interleaved [(K/2) x N] half2 -> LDS.32 fragments (proven)
// Pure fp16 MMA (fp32 accumulate). CTA 128x64, BK=64, 3-stage cp.async.
// ============================================================
#define BM 128
#define BN 64
#define BK 64
#define APITCH 72                      // halfs per A smem row (144 B); ldmatrix quads distinct
#define BPITCH32 72                    // uint32 per B smem row (288 B); banks 8p+n conflict-free
#define A_BYTES (BM * APITCH * 2)      // 18432
#define B_BYTES (32 * BPITCH32 * 4)    // 9216 (32 pair-rows)
#define STAGE_BYTES (A_BYTES + B_BYTES)        // 27648
#define STAGES 3
#define GEMM_SMEM_BYTES (STAGES * STAGE_BYTES) // 82944

template<int RELU>   // 1: fp16 out (next layer's A); 0: fp32 out
__global__ void __launch_bounds__(256, 2) k_gemm(
    const __half* __restrict__ A, const __half* __restrict__ W,
    const float* __restrict__ bias, void* __restrict__ outp,
    int M, int N, int K)
{
    extern __shared__ char smem[];
    const int tid  = threadIdx.x;
    const int lane = tid & 31;
    const int wid  = tid >> 5;
    const int wm   = wid & 3;        // 4 warps in M -> 32 rows each
    const int wn   = wid >> 2;       // 2 warps in N -> 32 cols each
    const int m0   = blockIdx.y * BM;
    const int n0   = blockIdx.x * BN;
    const int r    = lane >> 2;      // 0..7
    const int q    = lane & 3;       // 0..3

    // ldmatrix source row/col for this lane (within a 16x16 A tile):
    //  lanes 0-15 -> rows 0-15 of k-lo half; lanes 16-31 -> rows 0-15 of k-hi (+8)
    const int lrow = lane & 15;
    const int lkof = (lane >> 4) << 3;   // 0 or 8 (halfs)

    float c[2][4][4];
#pragma unroll
    for (int i = 0; i < 2; i++)
#pragma unroll
        for (int j = 0; j < 4; j++)
#pragma unroll
            for (int k = 0; k < 4; k++) c[i][j][k] = 0.f;

    const int kIters = K / BK;
    const uint32_t* Wp = (const uint32_t*)W;

    auto loadStage = [&](int it, int stg) {
        const int k0 = it * BK;
        char* st = smem + stg * STAGE_BYTES;
        // A: 128 rows x 8 chunks of 16B = 1024 chunks, 4 per thread
#pragma unroll
        for (int t = 0; t < 4; t++) {
            int id = tid + t * 256;
            int rr = id >> 3, ch = id & 7;
            const __half* src = A + (size_t)(m0 + rr) * K + k0 + ch * 8;
            cp16(st + rr * (APITCH * 2) + ch * 16, src);
        }
        // B: 32 pair-rows x 16 chunks of 16B = 512 chunks, 2 per thread
#pragma unroll
        for (int t = 0; t < 2; t++) {
            int id = tid + t * 256;
            int rr = id >> 4, ch = id & 15;
            const uint32_t* src = Wp + (size_t)(k0 / 2 + rr) * N + n0 + ch * 4;
            cp16(st + A_BYTES + rr * (BPITCH32 * 4) + ch * 16, src);
        }
    };

    loadStage(0, 0); CP_COMMIT();
    loadStage(1, 1); CP_COMMIT();

    int stg = 0;
    for (int it = 0; it < kIters; ++it) {
        CP_WAIT1();
        __syncthreads();
        if (it + 2 < kIters) loadStage(it + 2, (stg + 2) % STAGES);
        CP_COMMIT();

        const char* st = smem + stg * STAGE_BYTES;
        const uint32_t sAu = smem_u32(st);
        const uint32_t* sB = (const uint32_t*)(st + A_BYTES);

#pragma unroll
        for (int kk = 0; kk < BK; kk += 16) {
            uint32_t ah[2][4], bh[4][2];
#pragma unroll
            for (int mt = 0; mt < 2; mt++) {
                const uint32_t addr = sAu
                    + (uint32_t)(wm * 32 + mt * 16 + lrow) * (APITCH * 2)
                    + (uint32_t)(kk + lkof) * 2;
                LDSM_X4(ah[mt], addr);
            }
            const int p0 = (kk >> 1) + q;                 // pair row
#pragma unroll
            for (int nt = 0; nt < 4; nt++) {
                const int n  = wn * 32 + nt * 8 + r;
                const int i0 = p0 * BPITCH32 + n;
                bh[nt][0] = sB[i0];
                bh[nt][1] = sB[i0 + 4 * BPITCH32];
            }
#pragma unroll
            for (int mt = 0; mt < 2; mt++)
#pragma unroll
                for (int nt = 0; nt < 4; nt++)
                    MMA_F16(c[mt][nt], ah[mt], bh[nt]);
        }
        stg = (stg + 1) % STAGES;
    }

    // ---------------- epilogue ----------------
#pragma unroll
    for (int mt = 0; mt < 2; mt++) {
#pragma unroll
        for (int nt = 0; nt < 4; nt++) {
            int row0 = m0 + wm * 32 + mt * 16 + r;
            int col0 = n0 + wn * 32 + nt * 8 + 2 * q;
            float bb0 = bias[col0], bb1 = bias[col0 + 1];
            float v00 = c[mt][nt][0] + bb0, v01 = c[mt][nt][1] + bb1;
            float v10 = c[mt][nt][2] + bb0, v11 = c[mt][nt][3] + bb1;
            if (RELU) {
                __half2 p0 = __floats2half2_rn(fmaxf(v00, 0.f), fmaxf(v01, 0.f));
                __half2 p1 = __floats2half2_rn(fmaxf(v10, 0.f), fmaxf(v11, 0.f));
                __half* z = (__half*)outp;
                *(__half2*)&z[(size_t)row0 * N + col0]       = p0;
                *(__half2*)&z[(size_t)(row0 + 8) * N + col0] = p1;
            } else {
                float* o = (float*)outp;
                *(float2*)&o[(size_t)row0 * N + col0]       = make_float2(v00, v01);
                *(float2*)&o[(size_t)(row0 + 8) * N + col0] = make_float2(v10, v11);
            }
        }
    }
}

// ============================================================
// launch
// ============================================================
extern "C" void kernel_launch(void* const* d_in, const int* in_sizes, int n_in,
                              void* d_out, int out_size) {
    const float* x  = (const float*)d_in[0];
    const int*   ei = (const int*)  d_in[1];
    const float* gw = (const float*)d_in[2];
    const float* gb = (const float*)d_in[3];
    const float* W1 = (const float*)d_in[4];
    const float* b1 = (const float*)d_in[5];
    const float* W2 = (const float*)d_in[6];
    const float* b2 = (const float*)d_in[7];
    const float* W3 = (const float*)d_in[8];
    const float* b3 = (const float*)d_in[9];
    float* out = (float*)d_out;

    cudaFuncSetAttribute(k_gemm<1>, cudaFuncAttributeMaxDynamicSharedMemorySize, GEMM_SMEM_BYTES);
    cudaFuncSetAttribute(k_gemm<0>, cudaFuncAttributeMaxDynamicSharedMemorySize, GEMM_SMEM_BYTES);

    void *z0p, *z1p, *z2p, *w1p, *w2p, *w3p;
    cudaGetSymbolAddress(&z0p, g_z0);
    cudaGetSymbolAddress(&z1p, g_z1);
    cudaGetSymbolAddress(&z2p, g_z2);
    cudaGetSymbolAddress(&w1p, g_w1);
    cudaGetSymbolAddress(&w2p, g_w2);
    cudaGetSymbolAddress(&w3p, g_w3);

    // fused init + weight convert (k-pair-interleaved fp16)
    k_wconv_all<<<(N1_8 + N2_8 + N3_8) / 256, 256>>>(W1, W2, W3);

    // GCN
    k_count<<<NEDGE / 256, 256>>>(ei);
    k_scatter<<<NEDGE / 256, 256>>>(ei, x, gw);
    k_build_z<<<dim3(XDIMv / 2 / 256, BATCH), 256>>>(x, gw, gb);

    // MLP
    dim3 g1(H1v / BN,   BATCH / BM);
    dim3 g2(H2v / BN,   BATCH / BM);
    dim3 g3(YDIMv / BN, BATCH / BM);
    k_gemm<1><<<g1, 256, GEMM_SMEM_BYTES>>>(
        (const __half*)z0p, (const __half*)w1p, b1, z1p, BATCH, H1v, XDIMv);
    k_gemm<1><<<g2, 256, GEMM_SMEM_BYTES>>>(
        (const __half*)z1p, (const __half*)w2p, b2, z2p, BATCH, H2v, H1v);
    k_gemm<0><<<g3, 256, GEMM_SMEM_BYTES>>>(
        (const __half*)z2p, (const __half*)w3p, b3, out, BATCH, YDIMv, H2v);
}